// round 4
// baseline (speedup 1.0000x reference)
#include <cuda_runtime.h>

// Neo-Hookean 3D material point: psi, Cauchy (Voigt 6), DDSDDE (6x6) per point.
// Output layout (flattened tuple): [N] psi | [N,6] Cauchy6 | [N,36] DDSDDE.
//
// R3: (a) cau stored DIRECTLY (warp's cau region is contiguous: 3x STG.64
// spanning 768B/warp), removing its smem round-trip; (b) dd staging pitch
// 36 (stride 36 % 32 = 4 -> conflict-free, 16B aligned) shrinking smem to
// 36.9KB so 6 blocks/SM fit; (c) __launch_bounds__(256,6) to cap regs at 42.
// Goal: occupancy 56% -> ~75%, less L1 crossbar traffic.

#define TPB 256
#define ROW 36

__device__ __forceinline__ void nh3d_point(
    const float F[3][3], float c1, float c2,
    float& psi, float cau[6], float dd[36])
{
    // B = F F^T (symmetric)
    float B[3][3];
    #pragma unroll
    for (int i = 0; i < 3; i++)
        #pragma unroll
        for (int j = 0; j < 3; j++)
            B[i][j] = F[i][0]*F[j][0] + F[i][1]*F[j][1] + F[i][2]*F[j][2];

    float J = F[0][0]*(F[1][1]*F[2][2] - F[1][2]*F[2][1])
            - F[0][1]*(F[1][0]*F[2][2] - F[1][2]*F[2][0])
            + F[0][2]*(F[1][0]*F[2][1] - F[1][1]*F[2][0]);

    float I1   = B[0][0] + B[1][1] + B[2][2];
    float Jm23 = 1.0f / cbrtf(J * J);      // J^{-2/3}
    float invJ = 1.0f / J;

    float a = 2.0f * c1 * Jm23;
    float b = 2.0f * c2 * (J - 1.0f) * J;

    // Kirchhoff stress tau = a*(B - I1/3 * I) + b*I
    float tau[3][3];
    #pragma unroll
    for (int i = 0; i < 3; i++)
        #pragma unroll
        for (int j = 0; j < 3; j++)
            tau[i][j] = a * (B[i][j] - (i == j ? I1 * (1.0f/3.0f) : 0.0f))
                      + (i == j ? b : 0.0f);

    psi = c1 * (Jm23 * I1 - 3.0f) + c2 * (J - 1.0f) * (J - 1.0f);

    // Spatial tangent:
    // Stiff_ijkl = c_dd d_ij d_kl + c_bd (B_ij d_kl + d_ij B_kl)
    //            + a d_ik B_jl + c_sw d_il d_jk
    //            + 0.5*(tau_ik d_jl + tau_il d_jk + tau_jk d_il - tau_jl d_ik)
    float c_dd = (2.0f/9.0f) * a * I1 + 2.0f * c2 * (2.0f*J - 1.0f) * J;
    float c_bd = -(2.0f/3.0f) * a;
    float c_sw = a * I1 * (1.0f/3.0f) - b;

    const int II[6] = {0, 1, 2, 0, 0, 1};
    const int JJ[6] = {0, 1, 2, 1, 2, 2};

    #pragma unroll
    for (int r = 0; r < 6; r++)
        cau[r] = tau[II[r]][JJ[r]] * invJ;

    #pragma unroll
    for (int r = 0; r < 6; r++) {
        const int i = II[r], j = JJ[r];
        #pragma unroll
        for (int c = 0; c < 6; c++) {
            const int k = II[c], l = JJ[c];
            float s = 0.0f;
            if (i == j && k == l) s += c_dd;
            if (k == l)           s += c_bd * B[i][j];
            if (i == j)           s += c_bd * B[k][l];
            if (i == k)           s += a * B[j][l];
            if (i == l && j == k) s += c_sw;
            float g = 0.0f;
            if (j == l) g += tau[i][k];
            if (j == k) g += tau[i][l];
            if (i == l) g += tau[j][k];
            if (i == k) g -= tau[j][l];
            s += 0.5f * g;
            dd[r*6 + c] = s * invJ;
        }
    }
}

__global__ __launch_bounds__(TPB, 6) void nh3d_kernel(
    const float* __restrict__ F_in,
    const float* __restrict__ mat_par,
    float* __restrict__ out,
    int n, int vec_ok)
{
    __shared__ float sbuf[TPB * ROW];   // 36864 B -> 6 blocks/SM

    const int tid = threadIdx.x;
    const int block_start = blockIdx.x * TPB;
    const float c1 = mat_par[0];
    const float c2 = mat_par[1];

    float F[3][3];
    float psi, cau[6], dd[36];

    if (vec_ok && block_start + TPB <= n) {
        // ---------------- full block: staged, vectorized path ----------------
        // Stage F: 256*9 floats = 576 float4, coalesced LDG.128 -> STS.128
        {
            const float4* g4 = reinterpret_cast<const float4*>(F_in + (size_t)block_start * 9);
            float4* s4 = reinterpret_cast<float4*>(sbuf);
            #pragma unroll
            for (int v = tid; v < (TPB * 9) / 4; v += TPB)
                s4[v] = __ldcs(g4 + v);
        }
        __syncthreads();
        #pragma unroll
        for (int i = 0; i < 9; i++)
            (&F[0][0])[i] = sbuf[tid * 9 + i];   // stride 9: conflict-free
        __syncthreads();   // all F reads done before results overwrite sbuf

        nh3d_point(F, c1, c2, psi, cau, dd);

        // psi: coalesced STG.32
        __stcs(out + block_start + tid, psi);

        // cau: DIRECT stores — warp region is contiguous (32*24B = 768B/instr set)
        {
            float2* c2p = reinterpret_cast<float2*>(out + (size_t)n + (size_t)(block_start + tid) * 6);
            __stcs(c2p + 0, make_float2(cau[0], cau[1]));
            __stcs(c2p + 1, make_float2(cau[2], cau[3]));
            __stcs(c2p + 2, make_float2(cau[4], cau[5]));
        }

        // stage dd: pitch 36 (stride%32==4 -> conflict-free STS.128)
        {
            float4* row4 = reinterpret_cast<float4*>(sbuf + tid * ROW);
            #pragma unroll
            for (int q = 0; q < 9; q++)
                row4[q] = make_float4(dd[4*q+0], dd[4*q+1], dd[4*q+2], dd[4*q+3]);
        }
        __syncthreads();

        // drain dd: 2304 float4 per block, LDS.128 -> coalesced STG.128
        {
            float4* ddst = reinterpret_cast<float4*>(out + (size_t)n * 7 + (size_t)block_start * 36);
            #pragma unroll
            for (int k = 0; k < 9; k++) {
                int t4 = tid + k * TPB;
                int p = t4 / 9, q4 = t4 - p * 9;
                float4 v = *reinterpret_cast<const float4*>(sbuf + p * ROW + q4 * 4);
                __stcs(ddst + t4, v);
            }
        }
    } else {
        // ---------------- tail / unaligned fallback: scalar path ----------------
        const int p = block_start + tid;
        if (p >= n) return;
        const float* Fp = F_in + (size_t)p * 9;
        #pragma unroll
        for (int i = 0; i < 9; i++)
            (&F[0][0])[i] = __ldcs(Fp + i);

        nh3d_point(F, c1, c2, psi, cau, dd);

        __stcs(out + p, psi);
        float* cbase = out + (size_t)n + (size_t)p * 6;
        #pragma unroll
        for (int q = 0; q < 6; q++) __stcs(cbase + q, cau[q]);
        float* dbase = out + (size_t)n * 7 + (size_t)p * 36;
        #pragma unroll
        for (int q = 0; q < 36; q++) __stcs(dbase + q, dd[q]);
    }
}

extern "C" void kernel_launch(void* const* d_in, const int* in_sizes, int n_in,
                              void* d_out, int out_size) {
    const float* F_in    = (const float*)d_in[0];
    const float* mat_par = (const float*)d_in[1];
    float* out = (float*)d_out;
    int n = in_sizes[0] / 9;

    // vector path alignment: dd base (7n floats) needs 16B (n%4==0),
    // cau base (n floats) + per-thread float2 need 8B (n%2==0).
    int vec_ok = ((n % 4) == 0) ? 1 : 0;

    int blocks = (n + TPB - 1) / TPB;
    nh3d_kernel<<<blocks, TPB>>>(F_in, mat_par, out, n, vec_ok);
}

// round 5
// speedup vs baseline: 1.0563x; 1.0563x over previous
#include <cuda_runtime.h>
#include <cstdint>

// Neo-Hookean 3D material point: psi, Cauchy (Voigt 6), DDSDDE (6x6) per point.
// Output layout (flattened tuple): [N] psi | [N,6] Cauchy6 | [N,36] DDSDDE.
//
// R4: bulk-TMA drain. dd is staged in smem with pitch 36 (byte-identical to
// the block's gmem dd region) and drained with ONE cp.async.bulk S2G per
// block; cau likewise (pitch 6, staged in the retired F buffer). This deletes
// the per-thread LDS.128+STG.128 drain (L1 was the binding pipe at ~59%).

#define TPB 256
#define ROW 36
#define DD_SMEM_FLOATS (TPB * ROW)          // 9216 floats = 36864 B
#define F_SMEM_FLOATS  (TPB * 9)            // 2304 floats = 9216 B (reused for cau)

__device__ __forceinline__ uint32_t smem_u32(const void* p) {
    uint32_t a;
    asm("{ .reg .u64 t; cvta.to.shared.u64 t, %1; cvt.u32.u64 %0, t; }"
        : "=r"(a) : "l"(p));
    return a;
}

__device__ __forceinline__ void nh3d_point(
    const float F[3][3], float c1, float c2,
    float& psi, float cau[6], float dd[36])
{
    // B = F F^T (symmetric)
    float B[3][3];
    #pragma unroll
    for (int i = 0; i < 3; i++)
        #pragma unroll
        for (int j = 0; j < 3; j++)
            B[i][j] = F[i][0]*F[j][0] + F[i][1]*F[j][1] + F[i][2]*F[j][2];

    float J = F[0][0]*(F[1][1]*F[2][2] - F[1][2]*F[2][1])
            - F[0][1]*(F[1][0]*F[2][2] - F[1][2]*F[2][0])
            + F[0][2]*(F[1][0]*F[2][1] - F[1][1]*F[2][0]);

    float I1   = B[0][0] + B[1][1] + B[2][2];
    float Jm23 = 1.0f / cbrtf(J * J);      // J^{-2/3}
    float invJ = 1.0f / J;

    float a = 2.0f * c1 * Jm23;
    float b = 2.0f * c2 * (J - 1.0f) * J;

    // Kirchhoff stress tau = a*(B - I1/3 * I) + b*I
    float tau[3][3];
    #pragma unroll
    for (int i = 0; i < 3; i++)
        #pragma unroll
        for (int j = 0; j < 3; j++)
            tau[i][j] = a * (B[i][j] - (i == j ? I1 * (1.0f/3.0f) : 0.0f))
                      + (i == j ? b : 0.0f);

    psi = c1 * (Jm23 * I1 - 3.0f) + c2 * (J - 1.0f) * (J - 1.0f);

    // Spatial tangent:
    // Stiff_ijkl = c_dd d_ij d_kl + c_bd (B_ij d_kl + d_ij B_kl)
    //            + a d_ik B_jl + c_sw d_il d_jk
    //            + 0.5*(tau_ik d_jl + tau_il d_jk + tau_jk d_il - tau_jl d_ik)
    float c_dd = (2.0f/9.0f) * a * I1 + 2.0f * c2 * (2.0f*J - 1.0f) * J;
    float c_bd = -(2.0f/3.0f) * a;
    float c_sw = a * I1 * (1.0f/3.0f) - b;

    const int II[6] = {0, 1, 2, 0, 0, 1};
    const int JJ[6] = {0, 1, 2, 1, 2, 2};

    #pragma unroll
    for (int r = 0; r < 6; r++)
        cau[r] = tau[II[r]][JJ[r]] * invJ;

    #pragma unroll
    for (int r = 0; r < 6; r++) {
        const int i = II[r], j = JJ[r];
        #pragma unroll
        for (int c = 0; c < 6; c++) {
            const int k = II[c], l = JJ[c];
            float s = 0.0f;
            if (i == j && k == l) s += c_dd;
            if (k == l)           s += c_bd * B[i][j];
            if (i == j)           s += c_bd * B[k][l];
            if (i == k)           s += a * B[j][l];
            if (i == l && j == k) s += c_sw;
            float g = 0.0f;
            if (j == l) g += tau[i][k];
            if (j == k) g += tau[i][l];
            if (i == l) g += tau[j][k];
            if (i == k) g -= tau[j][l];
            s += 0.5f * g;
            dd[r*6 + c] = s * invJ;
        }
    }
}

__global__ __launch_bounds__(TPB) void nh3d_kernel(
    const float* __restrict__ F_in,
    const float* __restrict__ mat_par,
    float* __restrict__ out,
    int n, int vec_ok)
{
    __shared__ __align__(16) float sdd[DD_SMEM_FLOATS];  // 36864 B: dd staging
    __shared__ __align__(16) float sfc[F_SMEM_FLOATS];   //  9216 B: F in, then cau

    const int tid = threadIdx.x;
    const int block_start = blockIdx.x * TPB;
    const float c1 = mat_par[0];
    const float c2 = mat_par[1];

    float F[3][3];
    float psi, cau[6], dd[36];

    if (vec_ok && block_start + TPB <= n) {
        // ---- stage F: 576 float4, coalesced LDG.128 -> STS.128 ----
        {
            const float4* g4 = reinterpret_cast<const float4*>(F_in + (size_t)block_start * 9);
            float4* s4 = reinterpret_cast<float4*>(sfc);
            #pragma unroll
            for (int v = tid; v < (TPB * 9) / 4; v += TPB)
                s4[v] = __ldcs(g4 + v);
        }
        __syncthreads();
        #pragma unroll
        for (int i = 0; i < 9; i++)
            (&F[0][0])[i] = sfc[tid * 9 + i];      // stride 9: conflict-free
        __syncthreads();   // F fully consumed before sfc is reused for cau

        nh3d_point(F, c1, c2, psi, cau, dd);

        // psi: coalesced STG.32 (optimal already)
        __stcs(out + block_start + tid, psi);

        // stage dd: pitch 36 == gmem layout (stride%32==4 -> conflict-free STS.128)
        {
            float4* row4 = reinterpret_cast<float4*>(sdd + tid * ROW);
            #pragma unroll
            for (int q = 0; q < 9; q++)
                row4[q] = make_float4(dd[4*q+0], dd[4*q+1], dd[4*q+2], dd[4*q+3]);
        }
        // stage cau: pitch 6 == gmem layout
        {
            float2* row2 = reinterpret_cast<float2*>(sfc + tid * 6);
            row2[0] = make_float2(cau[0], cau[1]);
            row2[1] = make_float2(cau[2], cau[3]);
            row2[2] = make_float2(cau[4], cau[5]);
        }
        __syncthreads();

        // ---- bulk async drain: smem -> gmem, one copy per region ----
        if (tid == 0) {
            asm volatile("fence.proxy.async.shared::cta;" ::: "memory");
            float* ddst = out + (size_t)n * 7 + (size_t)block_start * 36;
            float* cdst = out + (size_t)n     + (size_t)block_start * 6;
            uint32_t sdd_a = smem_u32(sdd);
            uint32_t sfc_a = smem_u32(sfc);
            asm volatile(
                "cp.async.bulk.global.shared::cta.bulk_group [%0], [%1], %2;"
                :: "l"(ddst), "r"(sdd_a), "n"(DD_SMEM_FLOATS * 4) : "memory");
            asm volatile(
                "cp.async.bulk.global.shared::cta.bulk_group [%0], [%1], %2;"
                :: "l"(cdst), "r"(sfc_a), "n"(TPB * 6 * 4) : "memory");
            asm volatile("cp.async.bulk.commit_group;" ::: "memory");
            asm volatile("cp.async.bulk.wait_group 0;" ::: "memory");
        }
    } else {
        // ---- tail / unaligned fallback: scalar path ----
        const int p = block_start + tid;
        if (p >= n) return;
        const float* Fp = F_in + (size_t)p * 9;
        #pragma unroll
        for (int i = 0; i < 9; i++)
            (&F[0][0])[i] = __ldcs(Fp + i);

        nh3d_point(F, c1, c2, psi, cau, dd);

        __stcs(out + p, psi);
        float* cbase = out + (size_t)n + (size_t)p * 6;
        #pragma unroll
        for (int q = 0; q < 6; q++) __stcs(cbase + q, cau[q]);
        float* dbase = out + (size_t)n * 7 + (size_t)p * 36;
        #pragma unroll
        for (int q = 0; q < 36; q++) __stcs(dbase + q, dd[q]);
    }
}

extern "C" void kernel_launch(void* const* d_in, const int* in_sizes, int n_in,
                              void* d_out, int out_size) {
    const float* F_in    = (const float*)d_in[0];
    const float* mat_par = (const float*)d_in[1];
    float* out = (float*)d_out;
    int n = in_sizes[0] / 9;

    // fast path needs 16B alignment of both gmem bulk destinations:
    // dd base (7n floats) and cau base (n floats) -> n % 4 == 0.
    int vec_ok = ((n % 4) == 0) ? 1 : 0;

    int blocks = (n + TPB - 1) / TPB;
    nh3d_kernel<<<blocks, TPB>>>(F_in, mat_par, out, n, vec_ok);
}

// round 6
// speedup vs baseline: 1.0572x; 1.0009x over previous
#include <cuda_runtime.h>
#include <cstdint>

// Neo-Hookean 3D material point: psi, Cauchy (Voigt 6), DDSDDE (6x6) per point.
// Output layout (flattened tuple): [N] psi | [N,6] Cauchy6 | [N,36] DDSDDE.
//
// R5: TMA bulk drain for dd only; cau goes out as direct contiguous STG.64
// (its region is thread-contiguous, no transpose needed). smem = 45KB ->
// 5 blocks/SM with __launch_bounds__(256,5) to recover the occupancy lost
// in R4 (regs had ballooned to 64, occ 32%).

#define TPB 256
#define ROW 36
#define DD_SMEM_FLOATS (TPB * ROW)          // 9216 floats = 36864 B
#define F_SMEM_FLOATS  (TPB * 9)            // 2304 floats = 9216 B

__device__ __forceinline__ uint32_t smem_u32(const void* p) {
    uint32_t a;
    asm("{ .reg .u64 t; cvta.to.shared.u64 t, %1; cvt.u32.u64 %0, t; }"
        : "=r"(a) : "l"(p));
    return a;
}

__device__ __forceinline__ void nh3d_point(
    const float F[3][3], float c1, float c2,
    float& psi, float cau[6], float dd[36])
{
    // B = F F^T (symmetric)
    float B[3][3];
    #pragma unroll
    for (int i = 0; i < 3; i++)
        #pragma unroll
        for (int j = 0; j < 3; j++)
            B[i][j] = F[i][0]*F[j][0] + F[i][1]*F[j][1] + F[i][2]*F[j][2];

    float J = F[0][0]*(F[1][1]*F[2][2] - F[1][2]*F[2][1])
            - F[0][1]*(F[1][0]*F[2][2] - F[1][2]*F[2][0])
            + F[0][2]*(F[1][0]*F[2][1] - F[1][1]*F[2][0]);

    float I1   = B[0][0] + B[1][1] + B[2][2];
    float Jm23 = 1.0f / cbrtf(J * J);      // J^{-2/3}
    float invJ = 1.0f / J;

    float a = 2.0f * c1 * Jm23;
    float b = 2.0f * c2 * (J - 1.0f) * J;

    // Kirchhoff stress tau = a*(B - I1/3 * I) + b*I
    float tau[3][3];
    #pragma unroll
    for (int i = 0; i < 3; i++)
        #pragma unroll
        for (int j = 0; j < 3; j++)
            tau[i][j] = a * (B[i][j] - (i == j ? I1 * (1.0f/3.0f) : 0.0f))
                      + (i == j ? b : 0.0f);

    psi = c1 * (Jm23 * I1 - 3.0f) + c2 * (J - 1.0f) * (J - 1.0f);

    // Spatial tangent:
    // Stiff_ijkl = c_dd d_ij d_kl + c_bd (B_ij d_kl + d_ij B_kl)
    //            + a d_ik B_jl + c_sw d_il d_jk
    //            + 0.5*(tau_ik d_jl + tau_il d_jk + tau_jk d_il - tau_jl d_ik)
    float c_dd = (2.0f/9.0f) * a * I1 + 2.0f * c2 * (2.0f*J - 1.0f) * J;
    float c_bd = -(2.0f/3.0f) * a;
    float c_sw = a * I1 * (1.0f/3.0f) - b;

    const int II[6] = {0, 1, 2, 0, 0, 1};
    const int JJ[6] = {0, 1, 2, 1, 2, 2};

    #pragma unroll
    for (int r = 0; r < 6; r++)
        cau[r] = tau[II[r]][JJ[r]] * invJ;

    #pragma unroll
    for (int r = 0; r < 6; r++) {
        const int i = II[r], j = JJ[r];
        #pragma unroll
        for (int c = 0; c < 6; c++) {
            const int k = II[c], l = JJ[c];
            float s = 0.0f;
            if (i == j && k == l) s += c_dd;
            if (k == l)           s += c_bd * B[i][j];
            if (i == j)           s += c_bd * B[k][l];
            if (i == k)           s += a * B[j][l];
            if (i == l && j == k) s += c_sw;
            float g = 0.0f;
            if (j == l) g += tau[i][k];
            if (j == k) g += tau[i][l];
            if (i == l) g += tau[j][k];
            if (i == k) g -= tau[j][l];
            s += 0.5f * g;
            dd[r*6 + c] = s * invJ;
        }
    }
}

__global__ __launch_bounds__(TPB, 5) void nh3d_kernel(
    const float* __restrict__ F_in,
    const float* __restrict__ mat_par,
    float* __restrict__ out,
    int n, int vec_ok)
{
    __shared__ __align__(16) float sdd[DD_SMEM_FLOATS];  // 36864 B: dd staging
    __shared__ __align__(16) float sf[F_SMEM_FLOATS];    //  9216 B: F staging

    const int tid = threadIdx.x;
    const int block_start = blockIdx.x * TPB;
    const float c1 = mat_par[0];
    const float c2 = mat_par[1];

    float F[3][3];
    float psi, cau[6], dd[36];

    if (vec_ok && block_start + TPB <= n) {
        // ---- stage F: 576 float4, coalesced LDG.128 -> STS.128 ----
        {
            const float4* g4 = reinterpret_cast<const float4*>(F_in + (size_t)block_start * 9);
            float4* s4 = reinterpret_cast<float4*>(sf);
            #pragma unroll
            for (int v = tid; v < (TPB * 9) / 4; v += TPB)
                s4[v] = __ldcs(g4 + v);
        }
        __syncthreads();
        #pragma unroll
        for (int i = 0; i < 9; i++)
            (&F[0][0])[i] = sf[tid * 9 + i];      // stride 9: conflict-free

        nh3d_point(F, c1, c2, psi, cau, dd);

        // psi: coalesced STG.32 — issue early
        __stcs(out + block_start + tid, psi);

        // cau: direct contiguous stores (warp region = 768 contiguous bytes)
        {
            float2* c2p = reinterpret_cast<float2*>(out + (size_t)n + (size_t)(block_start + tid) * 6);
            __stcs(c2p + 0, make_float2(cau[0], cau[1]));
            __stcs(c2p + 1, make_float2(cau[2], cau[3]));
            __stcs(c2p + 2, make_float2(cau[4], cau[5]));
        }

        // stage dd: pitch 36 == gmem layout (stride%32==4 -> conflict-free STS.128)
        {
            float4* row4 = reinterpret_cast<float4*>(sdd + tid * ROW);
            #pragma unroll
            for (int q = 0; q < 9; q++)
                row4[q] = make_float4(dd[4*q+0], dd[4*q+1], dd[4*q+2], dd[4*q+3]);
        }
        __syncthreads();

        // ---- bulk async drain: smem -> gmem, one copy per block ----
        if (tid == 0) {
            asm volatile("fence.proxy.async.shared::cta;" ::: "memory");
            float* ddst = out + (size_t)n * 7 + (size_t)block_start * 36;
            uint32_t sdd_a = smem_u32(sdd);
            asm volatile(
                "cp.async.bulk.global.shared::cta.bulk_group [%0], [%1], %2;"
                :: "l"(ddst), "r"(sdd_a), "n"(DD_SMEM_FLOATS * 4) : "memory");
            asm volatile("cp.async.bulk.commit_group;" ::: "memory");
            asm volatile("cp.async.bulk.wait_group 0;" ::: "memory");
        }
    } else {
        // ---- tail / unaligned fallback: scalar path ----
        const int p = block_start + tid;
        if (p >= n) return;
        const float* Fp = F_in + (size_t)p * 9;
        #pragma unroll
        for (int i = 0; i < 9; i++)
            (&F[0][0])[i] = __ldcs(Fp + i);

        nh3d_point(F, c1, c2, psi, cau, dd);

        __stcs(out + p, psi);
        float* cbase = out + (size_t)n + (size_t)p * 6;
        #pragma unroll
        for (int q = 0; q < 6; q++) __stcs(cbase + q, cau[q]);
        float* dbase = out + (size_t)n * 7 + (size_t)p * 36;
        #pragma unroll
        for (int q = 0; q < 36; q++) __stcs(dbase + q, dd[q]);
    }
}

extern "C" void kernel_launch(void* const* d_in, const int* in_sizes, int n_in,
                              void* d_out, int out_size) {
    const float* F_in    = (const float*)d_in[0];
    const float* mat_par = (const float*)d_in[1];
    float* out = (float*)d_out;
    int n = in_sizes[0] / 9;

    // fast path needs 16B alignment of the dd bulk destination (7n floats)
    // and 8B alignment of per-thread cau float2 -> n % 4 == 0.
    int vec_ok = ((n % 4) == 0) ? 1 : 0;

    int blocks = (n + TPB - 1) / TPB;
    nh3d_kernel<<<blocks, TPB>>>(F_in, mat_par, out, n, vec_ok);
}